// round 6
// baseline (speedup 1.0000x reference)
#include <cuda_runtime.h>
#include <cstdint>

// Problem constants
#define B  2
#define L  8192
#define D  1024
#define NFFT 16384
#define TPB 1024
#define NTW (3 * NFFT / 4)                    // 12288 twiddles: W^k, k < 3N/4
#define NPAD (NFFT + NFFT/16)
#define SMEM_BYTES (NPAD * sizeof(float2))    // 139264 B

// ---------------- device scratch ----------------
__device__ float  g_xt[(size_t)B * D * L];
__device__ float  g_ht[(size_t)D * L];
__device__ float2 g_hf[(size_t)D * NFFT];
__device__ float  g_yt[(size_t)B * D * L];
__device__ float2 g_tw[NTW];
__device__ int    g_qperm[NFFT];              // q[p] = rev4((N - rev4(p)) mod N)

// ---------------- helpers ----------------
__device__ __forceinline__ int pidx(int a) { return a + (a >> 4); }

__device__ __forceinline__ float2 cmul(float2 a, float2 b) {
    return make_float2(fmaf(a.x, b.x, -a.y * b.y),
                       fmaf(a.x, b.y,  a.y * b.x));
}
__device__ __forceinline__ float2 cadd(float2 a, float2 b) { return make_float2(a.x + b.x, a.y + b.y); }
__device__ __forceinline__ float2 csub(float2 a, float2 b) { return make_float2(a.x - b.x, a.y - b.y); }

__device__ __forceinline__ void bf4_dif(float2& a0, float2& a1, float2& a2, float2& a3) {
    float2 t0 = cadd(a0, a2), t1 = csub(a0, a2);
    float2 t2 = cadd(a1, a3), t3 = csub(a1, a3);
    a0 = cadd(t0, t2);
    a2 = csub(t0, t2);
    a1 = make_float2(t1.x + t3.y, t1.y - t3.x);  // t1 - i*t3
    a3 = make_float2(t1.x - t3.y, t1.y + t3.x);  // t1 + i*t3
}
__device__ __forceinline__ void bf4_dit(float2& a0, float2& a1, float2& a2, float2& a3) {
    float2 t0 = cadd(a0, a2), t1 = csub(a0, a2);
    float2 t2 = cadd(a1, a3), t3 = csub(a1, a3);
    a0 = cadd(t0, t2);
    a2 = csub(t0, t2);
    a1 = make_float2(t1.x - t3.y, t1.y + t3.x);  // t1 + i*t3
    a3 = make_float2(t1.x + t3.y, t1.y - t3.x);  // t1 - i*t3
}

__device__ __forceinline__ int rev4_14(int x) {
    int r = 0;
#pragma unroll
    for (int i = 0; i < 7; i++) { r = (r << 2) | (x & 3); x >>= 2; }
    return r;
}

// ---------------- init: twiddles + Hermitian-pair permutation ----------------
__global__ void init_kernel() {
    int k = blockIdx.x * blockDim.x + threadIdx.x;
    if (k < NTW) {
        float s, c;
        sincospif(-2.0f * (float)k / (float)NFFT, &s, &c);
        g_tw[k] = make_float2(c, s);
    }
    if (k < NFFT) {
        g_qperm[k] = rev4_14((NFFT - rev4_14(k)) & (NFFT - 1));
    }
}

// ---------------- tiled transpose: in[R][C] -> out[C][R], batched over z ----------------
__global__ void transpose_kernel(const float* __restrict__ in, float* __restrict__ out,
                                 int R, int C) {
    __shared__ float t[32][33];
    size_t zoff = (size_t)blockIdx.z * (size_t)R * (size_t)C;
    int c = blockIdx.x * 32 + threadIdx.x;
    int rbase = blockIdx.y * 32;
#pragma unroll
    for (int i = threadIdx.y; i < 32; i += 8)
        t[i][threadIdx.x] = in[zoff + (size_t)(rbase + i) * C + c];
    __syncthreads();
    int r = rbase + threadIdx.x;
    int cbase = blockIdx.x * 32;
#pragma unroll
    for (int i = threadIdx.y; i < 32; i += 8)
        out[zoff + (size_t)(cbase + i) * R + r] = t[threadIdx.x][i];
}

// ---------------- forward: combined DIF stages (LS, LS-2) in registers ----------------
// TPB == NFFT/16: each thread owns one radix-16 group.
// pidx strength-reduced: base_low4 + off_low4 never carries (verified per stage),
// so address = pidx(base) + off + (off>>4) with off compile-time.
template<int LS>
__device__ __forceinline__ void dif_pair(float2* sd, int tid) {
    constexpr int Q2 = 1 << (LS - 4);
    constexpr int Q  = 1 << (LS - 2);
    constexpr int S  = 1 << (14 - LS);
    __syncthreads();
    const int j2 = tid & (Q2 - 1);
    const int g  = tid >> (LS - 4);
    const int base = (g << LS) + j2;
    const int pb = base + (base >> 4);
    float2 v[4][4];
#pragma unroll
    for (int r = 0; r < 4; r++)
#pragma unroll
        for (int s = 0; s < 4; s++) {
            const int off = r * Q2 + s * Q;
            v[r][s] = sd[pb + off + (off >> 4)];
        }
    // level 1 = stage LS
#pragma unroll
    for (int r = 0; r < 4; r++) {
        bf4_dif(v[r][0], v[r][1], v[r][2], v[r][3]);
        const int i1 = (j2 + r * Q2) * S;
        float2 w  = g_tw[i1];
        float2 w2 = g_tw[2 * i1];
        float2 w3 = g_tw[3 * i1];
        v[r][1] = cmul(v[r][1], w);
        v[r][2] = cmul(v[r][2], w2);
        v[r][3] = cmul(v[r][3], w3);
    }
    // level 2 = stage LS-2
    {
        const int i2 = j2 * (4 * S);
        float2 wb  = g_tw[i2];
        float2 wb2 = g_tw[2 * i2];
        float2 wb3 = g_tw[3 * i2];
#pragma unroll
        for (int s = 0; s < 4; s++) {
            bf4_dif(v[0][s], v[1][s], v[2][s], v[3][s]);
            v[1][s] = cmul(v[1][s], wb);
            v[2][s] = cmul(v[2][s], wb2);
            v[3][s] = cmul(v[3][s], wb3);
        }
    }
#pragma unroll
    for (int r = 0; r < 4; r++)
#pragma unroll
        for (int s = 0; s < 4; s++) {
            const int off = r * Q2 + s * Q;
            sd[pb + off + (off >> 4)] = v[r][s];
        }
}

// final DIF stage ls=2 (q=1, twiddle = 1)
__device__ __forceinline__ void dif_last(float2* sd, int tid) {
    __syncthreads();
#pragma unroll
    for (int tt = 0; tt < (NFFT / 4) / TPB; ++tt) {
        int t = tid + tt * TPB;
        int pb = 4 * t + (t >> 2);
        float2 a0 = sd[pb + 0];
        float2 a1 = sd[pb + 1];
        float2 a2 = sd[pb + 2];
        float2 a3 = sd[pb + 3];
        bf4_dif(a0, a1, a2, a3);
        sd[pb + 0] = a0;
        sd[pb + 1] = a1;
        sd[pb + 2] = a2;
        sd[pb + 3] = a3;
    }
}

// first DIT stage ls=2
__device__ __forceinline__ void dit_first(float2* sd, int tid) {
    __syncthreads();
#pragma unroll
    for (int tt = 0; tt < (NFFT / 4) / TPB; ++tt) {
        int t = tid + tt * TPB;
        int pb = 4 * t + (t >> 2);
        float2 a0 = sd[pb + 0];
        float2 a1 = sd[pb + 1];
        float2 a2 = sd[pb + 2];
        float2 a3 = sd[pb + 3];
        bf4_dit(a0, a1, a2, a3);
        sd[pb + 0] = a0;
        sd[pb + 1] = a1;
        sd[pb + 2] = a2;
        sd[pb + 3] = a3;
    }
}

// combined DIT stages (LSA, LSA+2) in registers
template<int LSA>
__device__ __forceinline__ void dit_pair(float2* sd, int tid) {
    constexpr int QA   = 1 << (LSA - 2);
    constexpr int SA   = 1 << (14 - LSA);
    constexpr int QB   = 1 << LSA;
    constexpr int SB   = SA >> 2;
    constexpr int LENB = 1 << (LSA + 2);
    __syncthreads();
    const int j = tid & (QA - 1);
    const int G = tid >> (LSA - 2);
    const int base = G * LENB + j;
    const int pb = base + (base >> 4);
    float2 v[4][4];
#pragma unroll
    for (int r = 0; r < 4; r++)
#pragma unroll
        for (int s = 0; s < 4; s++) {
            const int off = r * QA + s * QB;
            v[r][s] = sd[pb + off + (off >> 4)];
        }
    // level A = stage LSA, conj twiddles idx j*SA
    {
        const int iA = j * SA;
        float2 w  = g_tw[iA];
        float2 w2 = g_tw[2 * iA];
        float2 w3 = g_tw[3 * iA];
        float2 wc  = make_float2(w.x,  -w.y);
        float2 wc2 = make_float2(w2.x, -w2.y);
        float2 wc3 = make_float2(w3.x, -w3.y);
#pragma unroll
        for (int s = 0; s < 4; s++) {
            v[1][s] = cmul(v[1][s], wc);
            v[2][s] = cmul(v[2][s], wc2);
            v[3][s] = cmul(v[3][s], wc3);
            bf4_dit(v[0][s], v[1][s], v[2][s], v[3][s]);
        }
    }
    // level B = stage LSA+2, conj twiddles idx (j + r*QA)*SB
#pragma unroll
    for (int r = 0; r < 4; r++) {
        const int iB = (j + r * QA) * SB;
        float2 w  = g_tw[iB];
        float2 w2 = g_tw[2 * iB];
        float2 w3 = g_tw[3 * iB];
        v[r][1] = cmul(v[r][1], make_float2(w.x,  -w.y));
        v[r][2] = cmul(v[r][2], make_float2(w2.x, -w2.y));
        v[r][3] = cmul(v[r][3], make_float2(w3.x, -w3.y));
        bf4_dit(v[r][0], v[r][1], v[r][2], v[r][3]);
    }
#pragma unroll
    for (int r = 0; r < 4; r++)
#pragma unroll
        for (int s = 0; s < 4; s++) {
            const int off = r * QA + s * QB;
            sd[pb + off + (off >> 4)] = v[r][s];
        }
}

__device__ __forceinline__ void fft_fwd(float2* sd, int tid) {
    dif_pair<14>(sd, tid);
    dif_pair<10>(sd, tid);
    dif_pair<6>(sd, tid);
    dif_last(sd, tid);
}
__device__ __forceinline__ void fft_inv(float2* sd, int tid) {
    dit_first(sd, tid);
    dit_pair<4>(sd, tid);
    dit_pair<8>(sd, tid);
    dit_pair<12>(sd, tid);
}

// ---------------- H spectra: TWO channels per block via Hermitian split ----------------
__global__ __launch_bounds__(TPB, 1)
void hfft_kernel() {
    extern __shared__ float2 sd[];
    const int tid = threadIdx.x;
    const int d0  = 2 * blockIdx.x;
    const int d1  = d0 + 1;

    const float* __restrict__ h0 = g_ht + (size_t)d0 * L;
    const float* __restrict__ h1 = g_ht + (size_t)d1 * L;
    for (int l = tid; l < L; l += TPB)        sd[pidx(l)] = make_float2(h0[l], h1[l]);
    for (int l = L + tid; l < NFFT; l += TPB) sd[pidx(l)] = make_float2(0.0f, 0.0f);

    fft_fwd(sd, tid);
    __syncthreads();

    float2* __restrict__ hf0 = g_hf + (size_t)d0 * NFFT;
    float2* __restrict__ hf1 = g_hf + (size_t)d1 * NFFT;
#pragma unroll
    for (int tt = 0; tt < NFFT / TPB; ++tt) {
        int p = tid + tt * TPB;
        int q = g_qperm[p];
        float2 zp = sd[p + (p >> 4)];
        float2 zq = sd[q + (q >> 4)];
        // H0 = (zp + conj(zq))/2 ; H1 = -i*(zp - conj(zq))/2
        hf0[p] = make_float2(0.5f * (zp.x + zq.x), 0.5f * (zp.y - zq.y));
        hf1[p] = make_float2(0.5f * (zp.y + zq.y), 0.5f * (zq.x - zp.x));
    }
}

// ---------------- conv: one channel per block, both batches packed re/im ----------------
__global__ __launch_bounds__(TPB, 1)
void conv_kernel(const float* __restrict__ bias) {
    extern __shared__ float2 sd[];
    const int tid = threadIdx.x;
    const int d   = blockIdx.x;

    const float* __restrict__ x0 = g_xt + (size_t)d * L;
    const float* __restrict__ x1 = g_xt + (size_t)(D + d) * L;
    for (int l = tid; l < L; l += TPB)        sd[pidx(l)] = make_float2(x0[l], x1[l]);
    for (int l = L + tid; l < NFFT; l += TPB) sd[pidx(l)] = make_float2(0.0f, 0.0f);

    fft_fwd(sd, tid);

    __syncthreads();
    const float2* __restrict__ hf = g_hf + (size_t)d * NFFT;
#pragma unroll
    for (int tt = 0; tt < NFFT / TPB; ++tt) {
        int k = tid + tt * TPB;
        int pk = k + (k >> 4);
        sd[pk] = cmul(sd[pk], hf[k]);
    }

    fft_inv(sd, tid);
    __syncthreads();

    const float invN = 1.0f / (float)NFFT;
    const float bd = bias[d];
    float* __restrict__ y0 = g_yt + (size_t)d * L;
    float* __restrict__ y1 = g_yt + (size_t)(D + d) * L;
    for (int l = tid; l < L; l += TPB) {
        float2 v = sd[pidx(l)];
        y0[l] = fmaf(v.x, invN, bd);
        y1[l] = fmaf(v.y, invN, bd);
    }
}

// ---------------- launch ----------------
extern "C" void kernel_launch(void* const* d_in, const int* in_sizes, int n_in,
                              void* d_out, int out_size) {
    const float* x    = (const float*)d_in[0];
    const float* h    = (const float*)d_in[1];
    const float* bias = (const float*)d_in[2];
    float* out = (float*)d_out;

    void *xt_p, *ht_p, *yt_p;
    cudaGetSymbolAddress(&xt_p, g_xt);
    cudaGetSymbolAddress(&ht_p, g_ht);
    cudaGetSymbolAddress(&yt_p, g_yt);

    cudaFuncSetAttribute(hfft_kernel, cudaFuncAttributeMaxDynamicSharedMemorySize, SMEM_BYTES);
    cudaFuncSetAttribute(conv_kernel, cudaFuncAttributeMaxDynamicSharedMemorySize, SMEM_BYTES);

    init_kernel<<<32, 512>>>();
    transpose_kernel<<<dim3(D / 32, L / 32, B), dim3(32, 8)>>>(x, (float*)xt_p, L, D);
    transpose_kernel<<<dim3(D / 32, L / 32, 1), dim3(32, 8)>>>(h, (float*)ht_p, L, D);
    hfft_kernel<<<D / 2, TPB, SMEM_BYTES>>>();
    conv_kernel<<<D, TPB, SMEM_BYTES>>>(bias);
    transpose_kernel<<<dim3(L / 32, D / 32, B), dim3(32, 8)>>>((const float*)yt_p, out, D, L);
}

// round 7
// speedup vs baseline: 1.5841x; 1.5841x over previous
#include <cuda_runtime.h>
#include <cstdint>

// Problem constants
#define B  2
#define L  8192
#define D  1024
#define NFFT 16384
#define TPB 1024
#define NTW (NFFT / 4)                        // 4096 twiddles = 32 KB (L1-resident)
#define NPAD (NFFT + NFFT/16)
#define SMEM_BYTES (NPAD * sizeof(float2))    // 139264 B

// ---------------- device scratch ----------------
__device__ float  g_xt[(size_t)B * D * L];
__device__ float  g_ht[(size_t)D * L];
__device__ float2 g_hf[(size_t)D * NFFT];
__device__ float  g_yt[(size_t)B * D * L];
__device__ float2 g_tw[NTW];

// ---------------- helpers ----------------
__device__ __forceinline__ int pidx(int a) { return a + (a >> 4); }

__device__ __forceinline__ float2 cmul(float2 a, float2 b) {
    return make_float2(fmaf(a.x, b.x, -a.y * b.y),
                       fmaf(a.x, b.y,  a.y * b.x));
}
__device__ __forceinline__ float2 cadd(float2 a, float2 b) { return make_float2(a.x + b.x, a.y + b.y); }
__device__ __forceinline__ float2 csub(float2 a, float2 b) { return make_float2(a.x - b.x, a.y - b.y); }

__device__ __forceinline__ void bf4_dif(float2& a0, float2& a1, float2& a2, float2& a3) {
    float2 t0 = cadd(a0, a2), t1 = csub(a0, a2);
    float2 t2 = cadd(a1, a3), t3 = csub(a1, a3);
    a0 = cadd(t0, t2);
    a2 = csub(t0, t2);
    a1 = make_float2(t1.x + t3.y, t1.y - t3.x);  // t1 - i*t3
    a3 = make_float2(t1.x - t3.y, t1.y + t3.x);  // t1 + i*t3
}
__device__ __forceinline__ void bf4_dit(float2& a0, float2& a1, float2& a2, float2& a3) {
    float2 t0 = cadd(a0, a2), t1 = csub(a0, a2);
    float2 t2 = cadd(a1, a3), t3 = csub(a1, a3);
    a0 = cadd(t0, t2);
    a2 = csub(t0, t2);
    a1 = make_float2(t1.x - t3.y, t1.y + t3.x);  // t1 + i*t3
    a3 = make_float2(t1.x + t3.y, t1.y - t3.x);  // t1 - i*t3
}

__device__ __forceinline__ int rev4_14(int x) {
    int r = 0;
#pragma unroll
    for (int i = 0; i < 7; i++) { r = (r << 2) | (x & 3); x >>= 2; }
    return r;
}

// ---------------- init: twiddles ----------------
__global__ void init_kernel() {
    int k = blockIdx.x * blockDim.x + threadIdx.x;
    if (k < NTW) {
        float s, c;
        sincospif(-2.0f * (float)k / (float)NFFT, &s, &c);
        g_tw[k] = make_float2(c, s);
    }
}

// ---------------- tiled transpose: in[R][C] -> out[C][R], batched over z ----------------
__global__ void transpose_kernel(const float* __restrict__ in, float* __restrict__ out,
                                 int R, int C) {
    __shared__ float t[32][33];
    size_t zoff = (size_t)blockIdx.z * (size_t)R * (size_t)C;
    int c = blockIdx.x * 32 + threadIdx.x;
    int rbase = blockIdx.y * 32;
#pragma unroll
    for (int i = threadIdx.y; i < 32; i += 8)
        t[i][threadIdx.x] = in[zoff + (size_t)(rbase + i) * C + c];
    __syncthreads();
    int r = rbase + threadIdx.x;
    int cbase = blockIdx.x * 32;
#pragma unroll
    for (int i = threadIdx.y; i < 32; i += 8)
        out[zoff + (size_t)(cbase + i) * R + r] = t[threadIdx.x][i];
}

// ---------------- fused first fwd stage (14+12) straight from gmem ----------------
// Upper half (indices >= 8192, s in {2,3}) is the zero padding: specialized butterfly.
// row0/row1 are the two real signals packed as (re, im).
__device__ __forceinline__ void stageA_fwd(const float* __restrict__ row0,
                                           const float* __restrict__ row1,
                                           float2* sd, int tid) {
    float2 v[4][4];
    const int pb = tid + (tid >> 4);
#pragma unroll
    for (int r = 0; r < 4; r++) {
        const int i0 = tid + r * 1024;          // s=0
        const int i1 = i0 + 4096;               // s=1
        float2 a0 = make_float2(__ldg(row0 + i0), __ldg(row1 + i0));
        float2 a1 = make_float2(__ldg(row0 + i1), __ldg(row1 + i1));
        // bf4_dif with a2=a3=0:
        float2 X0 = cadd(a0, a1);
        float2 X2 = csub(a0, a1);
        float2 X1 = make_float2(a0.x + a1.y, a0.y - a1.x);  // a0 - i*a1
        float2 X3 = make_float2(a0.x - a1.y, a0.y + a1.x);  // a0 + i*a1
        float2 w  = g_tw[tid + r * 1024];       // S=1
        float2 w2 = cmul(w, w);
        float2 w3 = cmul(w2, w);
        v[r][0] = X0;
        v[r][1] = cmul(X1, w);
        v[r][2] = cmul(X2, w2);
        v[r][3] = cmul(X3, w3);
    }
    // level 2 = stage 12: twiddle idx 4*tid
    {
        float2 wb  = g_tw[4 * tid];
        float2 wb2 = cmul(wb, wb);
        float2 wb3 = cmul(wb2, wb);
#pragma unroll
        for (int s = 0; s < 4; s++) {
            bf4_dif(v[0][s], v[1][s], v[2][s], v[3][s]);
            v[1][s] = cmul(v[1][s], wb);
            v[2][s] = cmul(v[2][s], wb2);
            v[3][s] = cmul(v[3][s], wb3);
        }
    }
#pragma unroll
    for (int r = 0; r < 4; r++)
#pragma unroll
        for (int s = 0; s < 4; s++) {
            const int off = r * 1024 + s * 4096;
            sd[pb + off + (off >> 4)] = v[r][s];
        }
}

// ---------------- combined DIF stages (LS, LS-2), smem in/out ----------------
template<int LS>
__device__ __forceinline__ void dif_pair(float2* sd, int tid) {
    constexpr int Q2 = 1 << (LS - 4);
    constexpr int Q  = 1 << (LS - 2);
    constexpr int S  = 1 << (14 - LS);
    __syncthreads();
    const int j2 = tid & (Q2 - 1);
    const int g  = tid >> (LS - 4);
    const int base = (g << LS) + j2;
    const int pb = base + (base >> 4);
    float2 v[4][4];
#pragma unroll
    for (int r = 0; r < 4; r++)
#pragma unroll
        for (int s = 0; s < 4; s++) {
            const int off = r * Q2 + s * Q;
            v[r][s] = sd[pb + off + (off >> 4)];
        }
#pragma unroll
    for (int r = 0; r < 4; r++) {
        bf4_dif(v[r][0], v[r][1], v[r][2], v[r][3]);
        float2 w  = g_tw[(j2 + r * Q2) * S];
        float2 w2 = cmul(w, w);
        float2 w3 = cmul(w2, w);
        v[r][1] = cmul(v[r][1], w);
        v[r][2] = cmul(v[r][2], w2);
        v[r][3] = cmul(v[r][3], w3);
    }
    {
        float2 wb  = g_tw[j2 * (4 * S)];
        float2 wb2 = cmul(wb, wb);
        float2 wb3 = cmul(wb2, wb);
#pragma unroll
        for (int s = 0; s < 4; s++) {
            bf4_dif(v[0][s], v[1][s], v[2][s], v[3][s]);
            v[1][s] = cmul(v[1][s], wb);
            v[2][s] = cmul(v[2][s], wb2);
            v[3][s] = cmul(v[3][s], wb3);
        }
    }
#pragma unroll
    for (int r = 0; r < 4; r++)
#pragma unroll
        for (int s = 0; s < 4; s++) {
            const int off = r * Q2 + s * Q;
            sd[pb + off + (off >> 4)] = v[r][s];
        }
}

// final DIF stage ls=2 (hfft only)
__device__ __forceinline__ void dif_last(float2* sd, int tid) {
    __syncthreads();
#pragma unroll
    for (int tt = 0; tt < (NFFT / 4) / TPB; ++tt) {
        int t = tid + tt * TPB;
        int pb = 4 * t + (t >> 2);
        float2 a0 = sd[pb + 0];
        float2 a1 = sd[pb + 1];
        float2 a2 = sd[pb + 2];
        float2 a3 = sd[pb + 3];
        bf4_dif(a0, a1, a2, a3);
        sd[pb + 0] = a0;
        sd[pb + 1] = a1;
        sd[pb + 2] = a2;
        sd[pb + 3] = a3;
    }
}

// combined DIT stages (LSA, LSA+2), smem in/out
template<int LSA>
__device__ __forceinline__ void dit_pair(float2* sd, int tid) {
    constexpr int QA   = 1 << (LSA - 2);
    constexpr int SA   = 1 << (14 - LSA);
    constexpr int QB   = 1 << LSA;
    constexpr int SB   = SA >> 2;
    constexpr int LENB = 1 << (LSA + 2);
    __syncthreads();
    const int j = tid & (QA - 1);
    const int G = tid >> (LSA - 2);
    const int base = G * LENB + j;
    const int pb = base + (base >> 4);
    float2 v[4][4];
#pragma unroll
    for (int r = 0; r < 4; r++)
#pragma unroll
        for (int s = 0; s < 4; s++) {
            const int off = r * QA + s * QB;
            v[r][s] = sd[pb + off + (off >> 4)];
        }
    {
        float2 w   = g_tw[j * SA];
        float2 wc  = make_float2(w.x, -w.y);
        float2 wc2 = cmul(wc, wc);
        float2 wc3 = cmul(wc2, wc);
#pragma unroll
        for (int s = 0; s < 4; s++) {
            v[1][s] = cmul(v[1][s], wc);
            v[2][s] = cmul(v[2][s], wc2);
            v[3][s] = cmul(v[3][s], wc3);
            bf4_dit(v[0][s], v[1][s], v[2][s], v[3][s]);
        }
    }
#pragma unroll
    for (int r = 0; r < 4; r++) {
        float2 w   = g_tw[(j + r * QA) * SB];
        float2 wc  = make_float2(w.x, -w.y);
        float2 wc2 = cmul(wc, wc);
        float2 wc3 = cmul(wc2, wc);
        v[r][1] = cmul(v[r][1], wc);
        v[r][2] = cmul(v[r][2], wc2);
        v[r][3] = cmul(v[r][3], wc3);
        bf4_dit(v[r][0], v[r][1], v[r][2], v[r][3]);
    }
#pragma unroll
    for (int r = 0; r < 4; r++)
#pragma unroll
        for (int s = 0; s < 4; s++) {
            const int off = r * QA + s * QB;
            sd[pb + off + (off >> 4)] = v[r][s];
        }
}

// ---------------- H spectra: TWO channels per block via Hermitian split ----------------
__global__ __launch_bounds__(TPB, 1)
void hfft_kernel() {
    extern __shared__ float2 sd[];
    const int tid = threadIdx.x;
    const int d0  = 2 * blockIdx.x;
    const int d1  = d0 + 1;

    stageA_fwd(g_ht + (size_t)d0 * L, g_ht + (size_t)d1 * L, sd, tid);
    dif_pair<10>(sd, tid);
    dif_pair<6>(sd, tid);
    dif_last(sd, tid);
    __syncthreads();

    float2* __restrict__ hf0 = g_hf + (size_t)d0 * NFFT;
    float2* __restrict__ hf1 = g_hf + (size_t)d1 * NFFT;
#pragma unroll
    for (int tt = 0; tt < NFFT / TPB; ++tt) {
        int p = tid + tt * TPB;
        int q = rev4_14((NFFT - rev4_14(p)) & (NFFT - 1));
        float2 zp = sd[p + (p >> 4)];
        float2 zq = sd[q + (q >> 4)];
        // H0 = (zp + conj(zq))/2 ; H1 = -i*(zp - conj(zq))/2
        hf0[p] = make_float2(0.5f * (zp.x + zq.x), 0.5f * (zp.y - zq.y));
        hf1[p] = make_float2(0.5f * (zp.y + zq.y), 0.5f * (zq.x - zp.x));
    }
}

// ---------------- conv: one channel per block, both batches packed re/im ----------------
__global__ __launch_bounds__(TPB, 1)
void conv_kernel(const float* __restrict__ bias) {
    extern __shared__ float2 sd[];
    const int tid = threadIdx.x;
    const int d   = blockIdx.x;

    // fwd: fused first stage from gmem, then two smem pair-stages
    stageA_fwd(g_xt + (size_t)d * L, g_xt + (size_t)(D + d) * L, sd, tid);
    dif_pair<10>(sd, tid);
    dif_pair<6>(sd, tid);

    // fused: dif_last + pointwise *H + dit_first  (all on slots 4t..4t+3)
    __syncthreads();
    const float2* __restrict__ hf = g_hf + (size_t)d * NFFT;
#pragma unroll
    for (int tt = 0; tt < (NFFT / 4) / TPB; ++tt) {
        int t = tid + tt * TPB;
        int pb = 4 * t + (t >> 2);
        float2 a0 = sd[pb + 0];
        float2 a1 = sd[pb + 1];
        float2 a2 = sd[pb + 2];
        float2 a3 = sd[pb + 3];
        bf4_dif(a0, a1, a2, a3);
        a0 = cmul(a0, hf[4 * t + 0]);
        a1 = cmul(a1, hf[4 * t + 1]);
        a2 = cmul(a2, hf[4 * t + 2]);
        a3 = cmul(a3, hf[4 * t + 3]);
        bf4_dit(a0, a1, a2, a3);
        sd[pb + 0] = a0;
        sd[pb + 1] = a1;
        sd[pb + 2] = a2;
        sd[pb + 3] = a3;
    }

    dit_pair<4>(sd, tid);
    dit_pair<8>(sd, tid);

    // fused final inverse stage (12+14): smem -> registers -> gmem (keep idx < L only)
    __syncthreads();
    {
        const int pb = tid + (tid >> 4);
        float2 v[4][4];
#pragma unroll
        for (int r = 0; r < 4; r++)
#pragma unroll
            for (int s = 0; s < 4; s++) {
                const int off = r * 1024 + s * 4096;
                v[r][s] = sd[pb + off + (off >> 4)];
            }
        // level A = stage 12: conj twiddles idx 4*tid
        {
            float2 w   = g_tw[4 * tid];
            float2 wc  = make_float2(w.x, -w.y);
            float2 wc2 = cmul(wc, wc);
            float2 wc3 = cmul(wc2, wc);
#pragma unroll
            for (int s = 0; s < 4; s++) {
                v[1][s] = cmul(v[1][s], wc);
                v[2][s] = cmul(v[2][s], wc2);
                v[3][s] = cmul(v[3][s], wc3);
                bf4_dit(v[0][s], v[1][s], v[2][s], v[3][s]);
            }
        }
        // level B = stage 14: conj twiddles idx tid + r*1024, butterfly over s
        const float invN = 1.0f / (float)NFFT;
        const float bd = bias[d];
        float* __restrict__ y0 = g_yt + (size_t)d * L;
        float* __restrict__ y1 = g_yt + (size_t)(D + d) * L;
#pragma unroll
        for (int r = 0; r < 4; r++) {
            float2 w   = g_tw[tid + r * 1024];
            float2 wc  = make_float2(w.x, -w.y);
            float2 wc2 = cmul(wc, wc);
            float2 wc3 = cmul(wc2, wc);
            v[r][1] = cmul(v[r][1], wc);
            v[r][2] = cmul(v[r][2], wc2);
            v[r][3] = cmul(v[r][3], wc3);
            bf4_dit(v[r][0], v[r][1], v[r][2], v[r][3]);
            // outputs with natural index < L are s in {0,1}
#pragma unroll
            for (int s = 0; s < 2; s++) {
                const int idx = tid + r * 1024 + s * 4096;
                y0[idx] = fmaf(v[r][s].x, invN, bd);
                y1[idx] = fmaf(v[r][s].y, invN, bd);
            }
        }
    }
}

// ---------------- launch ----------------
extern "C" void kernel_launch(void* const* d_in, const int* in_sizes, int n_in,
                              void* d_out, int out_size) {
    const float* x    = (const float*)d_in[0];
    const float* h    = (const float*)d_in[1];
    const float* bias = (const float*)d_in[2];
    float* out = (float*)d_out;

    void *xt_p, *ht_p, *yt_p;
    cudaGetSymbolAddress(&xt_p, g_xt);
    cudaGetSymbolAddress(&ht_p, g_ht);
    cudaGetSymbolAddress(&yt_p, g_yt);

    cudaFuncSetAttribute(hfft_kernel, cudaFuncAttributeMaxDynamicSharedMemorySize, SMEM_BYTES);
    cudaFuncSetAttribute(conv_kernel, cudaFuncAttributeMaxDynamicSharedMemorySize, SMEM_BYTES);

    init_kernel<<<8, 512>>>();
    transpose_kernel<<<dim3(D / 32, L / 32, B), dim3(32, 8)>>>(x, (float*)xt_p, L, D);
    transpose_kernel<<<dim3(D / 32, L / 32, 1), dim3(32, 8)>>>(h, (float*)ht_p, L, D);
    hfft_kernel<<<D / 2, TPB, SMEM_BYTES>>>();
    conv_kernel<<<D, TPB, SMEM_BYTES>>>(bias);
    transpose_kernel<<<dim3(L / 32, D / 32, B), dim3(32, 8)>>>((const float*)yt_p, out, D, L);
}